// round 17
// baseline (speedup 1.0000x reference)
#include <cuda_runtime.h>
#include <cstdint>

// ---------------------------------------------------------------------------
// GMP_34196529611440 : generalized memory polynomial, single fused kernel.
// Round 17 = R8 exactly (best: ITER=4, TPB=256, Horner, padded tile, 64 regs)
//            + MLP-batched tile phase:
//   * SPB == 4*TPB -> 4 compile-time strided iterations + 12-thread tail
//   * interior blocks: no per-element clamp, all LDGs front-batched (MLP~10)
// ---------------------------------------------------------------------------

typedef unsigned long long u64;

__device__ __forceinline__ u64 fma2(u64 a, u64 b, u64 c) {
    u64 d;
    asm("fma.rn.f32x2 %0, %1, %2, %3;" : "=l"(d) : "l"(a), "l"(b), "l"(c));
    return d;
}
__device__ __forceinline__ u64 pack2(float x, float y) {
    u64 r;
    asm("mov.b64 %0, {%1, %2};" : "=l"(r) : "f"(x), "f"(y));
    return r;
}
__device__ __forceinline__ void unpack2(u64 v, float& x, float& y) {
    asm("mov.b64 {%0, %1}, %2;" : "=f"(x), "=f"(y) : "l"(v));
}
__device__ __forceinline__ float sqrt_approx(float s) {
    float r;
    asm("sqrt.approx.f32 %0, %1;" : "=f"(r) : "f"(s));
    return r;
}

constexpr int ITER = 4;            // consecutive samples per thread
constexpr int TPB  = 256;
constexpr int SPB  = TPB * ITER;   // 1024 (divides N = 2^20)
constexpr int TILE = SPB + 12;     // samples blockStart-5 .. blockStart+SPB+6
// pad(i) = i + (i>>2)
constexpr int PTILE = (TILE - 1) + ((TILE - 1) >> 2) + 1;

// shared coefficient layout (complex {re,im} as u64):
//   [0..3]    c0tot[l]   (all k=0 constant terms folded per l)
//   [4..19]   E[l*4 + (k-1)]  k=1..4   (a merged with b/c m=0 terms)
//   [20..46]  B[l*9 + (m-1)*3 + (k-1)]  l<3, m=1..3, k=1..3
//   [47..73]  C[...same...]
constexpr int NCOEF = 74;

__global__ __launch_bounds__(TPB, 4)
void gmp_kernel(const float* __restrict__ xre, const float* __restrict__ xim,
                const float* __restrict__ a_re, const float* __restrict__ a_im,
                const float* __restrict__ b_re, const float* __restrict__ b_im,
                const float* __restrict__ c_re, const float* __restrict__ c_im,
                float* __restrict__ out, int N) {
    __shared__ u64 sP[PTILE];      // {p, p}   duplicated |x|
    __shared__ u64 sX[PTILE];      // {re, im}
    __shared__ float2 scoef[NCOEF];

    const int tid = threadIdx.x;
    const int blockStart = blockIdx.x * SPB;

    // ---- per-block coefficient merge (threads 0..73), cheap one-time work
    if (tid < NCOEF) {
        float re, im;
        if (tid < 4) {                 // c0tot[l]
            int l = tid;
            re = a_re[l]; im = a_im[l];
            if (l < 3) {
#pragma unroll
                for (int m = 0; m < 4; ++m) {
                    re += b_re[l * 4 + m] + c_re[l * 4 + m];
                    im += b_im[l * 4 + m] + c_im[l * 4 + m];
                }
            }
        } else if (tid < 20) {         // E[l][k], k=1..4
            int e = tid - 4, l = e >> 2, k = (e & 3) + 1;
            re = a_re[k * 4 + l]; im = a_im[k * 4 + l];
            if (l < 3 && k < 4) {      // merge b/c m=0
                int src = (k * 3 + l) * 4;
                re += b_re[src] + c_re[src];
                im += b_im[src] + c_im[src];
            }
        } else if (tid < 47) {         // B
            int e = tid - 20, l = e / 9, r9 = e % 9, m = r9 / 3 + 1, k = r9 % 3 + 1;
            int src = (k * 3 + l) * 4 + m;
            re = b_re[src]; im = b_im[src];
        } else {                       // C
            int e = tid - 47, l = e / 9, r9 = e % 9, m = r9 / 3 + 1, k = r9 % 3 + 1;
            int src = (k * 3 + l) * 4 + m;
            re = c_re[src]; im = c_im[src];
        }
        scoef[tid] = make_float2(re, im);
    }

    // ---- cooperative tile load, MLP-batched.
    // TILE = 4*TPB + 12: iterations s = tid + k*TPB (k=0..3), tail s = 4*TPB+tid.
    if (blockIdx.x > 0 && blockIdx.x + 1 < gridDim.x) {
        // interior: no clamping needed; front-batch ALL global loads
        float r[5], im5[5];
#pragma unroll
        for (int k = 0; k < 4; ++k) {
            const int g = blockStart - 5 + tid + k * TPB;
            r[k]   = xre[g];
            im5[k] = xim[g];
        }
        const bool tail = (tid < TILE - 4 * TPB);   // tid < 12
        if (tail) {
            const int g = blockStart - 5 + tid + 4 * TPB;
            r[4]   = xre[g];
            im5[4] = xim[g];
        }
#pragma unroll
        for (int k = 0; k < 4; ++k) {
            const int s = tid + k * TPB;
            const float p = sqrt_approx(fmaf(r[k], r[k], im5[k] * im5[k]));
            const int ps = s + (s >> 2);
            sX[ps] = pack2(r[k], im5[k]);
            sP[ps] = pack2(p, p);
        }
        if (tail) {
            const int s = tid + 4 * TPB;
            const float p = sqrt_approx(fmaf(r[4], r[4], im5[4] * im5[4]));
            const int ps = s + (s >> 2);
            sX[ps] = pack2(r[4], im5[4]);
            sP[ps] = pack2(p, p);
        }
    } else {
        // edge blocks: clipped path
#pragma unroll
        for (int s = tid; s < TILE; s += TPB) {
            int g = blockStart - 5 + s;
            g = max(g, 0);
            g = min(g, N - 1);
            float r = xre[g];
            float i = xim[g];
            float p = sqrt_approx(fmaf(r, r, i * i));
            int ps = s + (s >> 2);
            sX[ps] = pack2(r, i);
            sP[ps] = pack2(p, p);
        }
    }
    __syncthreads();

    const u64* sc = reinterpret_cast<const u64*>(scoef);
    const int pb5 = tid * 5;            // pad(tid*4)
    const int n0 = blockStart + tid * ITER;

    // window j = 0..11 corresponds to sample n0 + j - 5; padded index:
#define PIDX(j) (pb5 + (j) + ((j) >> 2))

    // |x| window in registers (12 u64, conflict-free loads, heavy reuse)
    u64 pp2[12];
#pragma unroll
    for (int j = 0; j < 12; ++j) pp2[j] = sP[PIDX(j)];

    float yr[ITER], yi[ITER];
#pragma unroll
    for (int it = 0; it < ITER; ++it) { yr[it] = 0.f; yi[it] = 0.f; }

#pragma unroll
    for (int l = 0; l < 4; ++l) {
        u64 wl[ITER];
        {
            const u64 c0 = sc[l];
#pragma unroll
            for (int it = 0; it < ITER; ++it) wl[it] = c0;
        }
        // E (deg 4): w += (((e4 p + e3) p + e2) p + e1) p   at p[n+it-l]
        {
            const u64 e1 = sc[4 + l * 4 + 0], e2 = sc[4 + l * 4 + 1],
                      e3 = sc[4 + l * 4 + 2], e4 = sc[4 + l * 4 + 3];
#pragma unroll
            for (int it = 0; it < ITER; ++it) {
                const u64 p = pp2[it - l + 5];
                u64 q = fma2(e4, p, e3);
                q = fma2(q, p, e2);
                q = fma2(q, p, e1);
                wl[it] = fma2(q, p, wl[it]);
            }
        }
        if (l < 3) {
#pragma unroll
            for (int m = 1; m < 4; ++m) {   // B at p[n+it-l-m]
                const int bb = 20 + l * 9 + (m - 1) * 3;
                const u64 b1 = sc[bb + 0], b2 = sc[bb + 1], b3 = sc[bb + 2];
#pragma unroll
                for (int it = 0; it < ITER; ++it) {
                    const u64 p = pp2[it - l - m + 5];
                    u64 q = fma2(b3, p, b2);
                    q = fma2(q, p, b1);
                    wl[it] = fma2(q, p, wl[it]);
                }
            }
#pragma unroll
            for (int m = 1; m < 4; ++m) {   // C at p[n+it-l+m]
                const int cb = 47 + l * 9 + (m - 1) * 3;
                const u64 c1 = sc[cb + 0], c2 = sc[cb + 1], c3 = sc[cb + 2];
#pragma unroll
                for (int it = 0; it < ITER; ++it) {
                    const u64 p = pp2[it - l + m + 5];
                    u64 q = fma2(c3, p, c2);
                    q = fma2(q, p, c1);
                    wl[it] = fma2(q, p, wl[it]);
                }
            }
        }
        // combine: y[n+it] += x[n+it-l] * w_l   (complex; x from padded shared)
#pragma unroll
        for (int it = 0; it < ITER; ++it) {
            float vr, vi;
            unpack2(wl[it], vr, vi);
            float r, i;
            unpack2(sX[PIDX(it - l + 5)], r, i);
            yr[it] = fmaf(r, vr, yr[it]);
            yr[it] = fmaf(-i, vi, yr[it]);
            yi[it] = fmaf(r, vi, yi[it]);
            yi[it] = fmaf(i, vr, yi[it]);
        }
    }
#undef PIDX

    // n0 is a multiple of 4 -> 16B-aligned float4 stores; SPB divides N
    if (n0 + ITER <= N) {
        *reinterpret_cast<float4*>(out + n0)     = make_float4(yr[0], yr[1], yr[2], yr[3]);
        *reinterpret_cast<float4*>(out + N + n0) = make_float4(yi[0], yi[1], yi[2], yi[3]);
    } else {
#pragma unroll
        for (int it = 0; it < ITER; ++it) {
            int n = n0 + it;
            if (n < N) { out[n] = yr[it]; out[N + n] = yi[it]; }
        }
    }
}

extern "C" void kernel_launch(void* const* d_in, const int* in_sizes, int n_in,
                              void* d_out, int out_size) {
    const float* x_re = (const float*)d_in[0];
    const float* x_im = (const float*)d_in[1];
    const float* a_re = (const float*)d_in[2];
    const float* a_im = (const float*)d_in[3];
    const float* b_re = (const float*)d_in[4];
    const float* b_im = (const float*)d_in[5];
    const float* c_re = (const float*)d_in[6];
    const float* c_im = (const float*)d_in[7];
    float* out = (float*)d_out;
    const int N = in_sizes[0];

    const int grid = (N + SPB - 1) / SPB;
    gmp_kernel<<<grid, TPB>>>(x_re, x_im, a_re, a_im, b_re, b_im,
                              c_re, c_im, out, N);
}